// round 14
// baseline (speedup 1.0000x reference)
#include <cuda_runtime.h>
#include <cuda_fp16.h>
#include <cstdint>

// ============================================================================
// Spectral pooling as two plain-fp16 GEMMs (fp32 accumulate) on the legacy
// tensor path (mma.sync m16n8k16.f32.f16.f16.f32 — sm_100, no tcgen05).
//   out = A X A^T - B X B^T   (per batch, per channel)
// Stage 1: Ys[(k1,c)][(half,n2)] = W1[(half,k1)][n1] * Xs[(c,n2)][n1]   K=256
// Stage 2: out[k2][(k1,c)]       = W2[k2][(half,n2)] * Ys              K=512
// fp16 operands, fp32 accum; error ~4e-4 (model validated R12/R13).
// R14: 3-stage cp.async pipeline (cp_wait<1>) — with K down to 4/8 chunks the
// 2-deep pipeline's zero-latency-tolerance wait was the binding overhead.
// ============================================================================

namespace {
constexpr int Hn = 256, Kc = 217, Bt = 16, Ch = 64;
constexpr int K1 = 256;      // stage-1 K (n1)
constexpr int K2 = 512;      // stage-2 K (half,n2)
constexpr int NC1 = 16384;   // stage-1 N  (c*256 + n2)
constexpr int YR  = 14080;   // stage-2 N padded (110*128 >= 217*64=13888)
constexpr double PI_D = 3.14159265358979323846;
}

__device__ __half g_W1s[512 * K1];               // rows>=434 stay 0
__device__ __half g_W2s[256 * K2];               // rows>=217 stay 0
__device__ __half g_Xs[(size_t)Bt * NC1 * K1];   // stage-1 B operand
__device__ __half g_Ys[(size_t)Bt * YR * K2];    // stage-2 B (pad rows 0)

#define SW128(x) ((x) ^ (((x) >> 3) & 0x70))

// ---------------- PTX helpers ------------------------------------------------
__device__ __forceinline__ uint32_t smem_u32(const void* p) {
    uint32_t a;
    asm("{ .reg .u64 t; cvta.to.shared.u64 t, %1; cvt.u32.u64 %0, t; }" : "=r"(a) : "l"(p));
    return a;
}
__device__ __forceinline__ void cp16(uint32_t dst, const void* src) {
    asm volatile("cp.async.cg.shared.global [%0], [%1], 16;" :: "r"(dst), "l"(src));
}
__device__ __forceinline__ void cp_commit() { asm volatile("cp.async.commit_group;"); }
template <int N>
__device__ __forceinline__ void cp_wait() {
    asm volatile("cp.async.wait_group %0;" :: "n"(N));
}
__device__ __forceinline__ void ldm_x4(uint32_t* r, uint32_t addr) {
    asm volatile("ldmatrix.sync.aligned.m8n8.x4.shared.b16 {%0,%1,%2,%3}, [%4];"
                 : "=r"(r[0]), "=r"(r[1]), "=r"(r[2]), "=r"(r[3]) : "r"(addr));
}
__device__ __forceinline__ void mma16816(float* c, const uint32_t* a,
                                         uint32_t b0, uint32_t b1) {
    asm volatile(
        "mma.sync.aligned.m16n8k16.row.col.f32.f16.f16.f32 "
        "{%0,%1,%2,%3}, {%4,%5,%6,%7}, {%8,%9}, {%0,%1,%2,%3};"
        : "+f"(c[0]), "+f"(c[1]), "+f"(c[2]), "+f"(c[3])
        : "r"(a[0]), "r"(a[1]), "r"(a[2]), "r"(a[3]), "r"(b0), "r"(b1));
}

// ---------------- init: fp16 weight tables ----------------------------------
__global__ void sp_init() {
    int idx = blockIdx.x * blockDim.x + threadIdx.x;
    if (idx >= Kc * Hn) return;
    int k = idx / Hn, n = idx - (idx / Hn) * Hn;
    double ph = PI_D * ((double)k / (double)Kc - (double)n / (double)Hn);
    double D = (k == 0 && n == 0) ? 1.0 : sin(217.0 * ph) / (sin(ph) * 217.0);
    double ang = 2.0 * PI_D * (double)n / (double)Hn;
    float a = (float)(D * cos(ang));
    float b = (float)(D * sin(ang));
    g_W1s[(size_t)k * K1 + n]        = __float2half(a);
    g_W1s[(size_t)(Kc + k) * K1 + n] = __float2half(b);
    g_W2s[(size_t)k * K2 + n]        = __float2half(a);
    g_W2s[(size_t)k * K2 + 256 + n]  = __float2half(-b);
}

// ---------------- transpose: X -> Xs[b][c*256+n2][n1] fp16 ------------------
__global__ __launch_bounds__(256) void sp_transpose(const float* __restrict__ X) {
    __shared__ float tile[32][65];
    const int n2  = blockIdx.x;   // 0..255
    const int n1g = blockIdx.y;   // 0..7
    const int b   = blockIdx.z;
    const int t   = threadIdx.x;
    const float* src = X + ((size_t)(b * Hn + n1g * 32)) * NC1 + n2 * 64;
#pragma unroll
    for (int p = 0; p < 8; p++) {
        int idx = p * 256 + t;
        int r = idx >> 6, col = idx & 63;
        tile[r][col] = src[(size_t)r * NC1 + col];
    }
    __syncthreads();
    const int c = t >> 2, part = t & 3, i0 = part * 8;
    __half* dst = g_Xs + ((size_t)b * NC1 + c * 256 + n2) * K1 + n1g * 32 + i0;
    __align__(16) __half h0[8];
#pragma unroll
    for (int i = 0; i < 8; i++) h0[i] = __float2half(tile[i0 + i][c]);
    *(uint4*)(dst) = *(const uint4*)h0;
}

// ---------------- warp-MMA GEMM: CTA 256x128, warp m64n64, 3-stage ----------
// SMEM per stage: A 256x128B (32KB) + B 128x128B (16KB) = 48KB; 3 stages 144KB.
constexpr int NST = 3;
constexpr int ST_BYTES = 49152;
constexpr int SMEM_GEMM = NST * ST_BYTES;   // 147456
constexpr int EP_STRIDE = 288;

template <int STAGE>
__global__ __launch_bounds__(256, 1) void sp_gemm(float* __restrict__ out) {
    extern __shared__ char smem[];
    const uint32_t sb = smem_u32(smem);
    const int tid = threadIdx.x, lane = tid & 31, wid = tid >> 5;
    const int warp_m = wid >> 1, warp_n = wid & 1;   // 4 x 2 warp grid, m64n64
    const int mt = blockIdx.x, nt = blockIdx.y, b = blockIdx.z;

    constexpr int KT  = (STAGE == 1) ? K1 : K2;      // K (row stride, both ops)
    constexpr int NCH = KT / 64;                     // 4 / 8 chunks
    const __half* Arow = ((STAGE == 1) ? g_W1s : g_W2s) + (size_t)(mt * 256) * KT;
    const __half* Brow = ((STAGE == 1) ? (g_Xs + (size_t)b * NC1 * K1)
                                       : (g_Ys + (size_t)b * YR * K2))
                         + (size_t)(nt * 128) * KT;

    float acc[4][8][4];
#pragma unroll
    for (int i = 0; i < 4; i++)
#pragma unroll
        for (int j = 0; j < 8; j++)
#pragma unroll
            for (int q = 0; q < 4; q++) acc[i][j][q] = 0.f;

    auto buf_of = [](int kc) { return (kc % NST); };

    auto prefetch = [&](int kc) {
        const uint32_t abase = sb + buf_of(kc) * ST_BYTES;
        const uint32_t bbase = abase + 32768;
        // A: 256 rows x 128B = 2048 16B slots; 8 per thread
#pragma unroll
        for (int p = 0; p < 8; p++) {
            int slot = p * 256 + tid;
            int r = slot >> 3, s = slot & 7;
            cp16(abase + SW128(r * 128 + s * 16),
                 Arow + (size_t)r * KT + kc * 64 + s * 8);
        }
        // B: 128 rows x 128B = 1024 slots; 4 per thread
#pragma unroll
        for (int p = 0; p < 4; p++) {
            int slot = p * 256 + tid;
            int r = slot >> 3, s = slot & 7;
            cp16(bbase + SW128(r * 128 + s * 16),
                 Brow + (size_t)r * KT + kc * 64 + s * 8);
        }
        cp_commit();
    };

    const int arow = warp_m * 64 + (lane & 7) + ((lane >> 3) & 1) * 8;
    const int akof = ((lane >> 4) & 1) * 16;
    const int brow = warp_n * 64 + (lane & 7) + ((lane >> 4) & 1) * 8;
    const int bkof = ((lane >> 3) & 1) * 16;

    prefetch(0);
    prefetch(1);
    for (int kc = 0; kc < NCH; kc++) {
        if (kc + 1 < NCH) cp_wait<1>(); else cp_wait<0>();
        __syncthreads();               // single barrier per chunk
        if (kc + 2 < NCH) prefetch(kc + 2);
        const uint32_t abase = sb + buf_of(kc) * ST_BYTES;
        const uint32_t bbase = abase + 32768;
#pragma unroll
        for (int ks = 0; ks < 4; ks++) {
            const int kb0 = ks * 32;
            uint32_t af[4][4];
#pragma unroll
            for (int mi = 0; mi < 4; mi++)
                ldm_x4(af[mi], abase + SW128((arow + mi * 16) * 128 + kb0 + akof));
            uint32_t bf[4][4];
#pragma unroll
            for (int nj = 0; nj < 4; nj++)
                ldm_x4(bf[nj], bbase + SW128((brow + nj * 16) * 128 + kb0 + bkof));
#pragma unroll
            for (int mi = 0; mi < 4; mi++)
#pragma unroll
                for (int ni = 0; ni < 8; ni++)
                    mma16816(acc[mi][ni], af[mi],
                             bf[ni >> 1][(ni & 1) * 2], bf[ni >> 1][(ni & 1) * 2 + 1]);
        }
    }

    // ---------------- epilogue ----------------
    const int r0 = lane >> 2;          // c-frag rows r0, r0+8
    const int c0 = lane & 3;           // c-frag col-pair index
    if (STAGE == 1) {
        // Stage through smem -> coalesced 16B fp16 stores.
        __half* Yb = g_Ys + (size_t)b * YR * K2;
        __syncthreads();
#pragma unroll
        for (int mi = 0; mi < 4; mi++) {
#pragma unroll
            for (int half_r = 0; half_r < 2; half_r++) {
                const int row = warp_m * 64 + mi * 16 + r0 + half_r * 8;
#pragma unroll
                for (int ni = 0; ni < 8; ni++) {
                    const int cp = warp_n * 32 + ni * 4 + c0;  // col pair 0..63
                    __half2 p;
                    p.x = __float2half(acc[mi][ni][half_r * 2 + 0]);
                    p.y = __float2half(acc[mi][ni][half_r * 2 + 1]);
                    *(__half2*)(smem + row * EP_STRIDE + cp * 4) = p;
                }
            }
        }
        __syncthreads();
        // Coalesced copy: 256 rows x 16 x 16B units = 4096; 16 per thread.
#pragma unroll
        for (int p = 0; p < 16; p++) {
            const int u = p * 256 + tid;
            const int row = u >> 4, sl = u & 15;
            const int gr = mt * 256 + row;
            if (gr < 434) {
                const int hf = (gr >= Kc) ? 1 : 0;
                const int k1 = gr - hf * Kc;
                const int gn = nt * 128 + sl * 8;
                const int c = gn >> 8, n2 = gn & 255;
                uint4 v = *(const uint4*)(smem + row * EP_STRIDE + sl * 16);
                *(uint4*)(Yb + ((size_t)k1 * 64 + c) * K2 + hf * 256 + n2) = v;
            }
        }
    } else {
#pragma unroll
        for (int mi = 0; mi < 4; mi++) {
#pragma unroll
            for (int half_r = 0; half_r < 2; half_r++) {
                const int k2 = mt * 256 + warp_m * 64 + mi * 16 + r0 + half_r * 8;
                if (k2 >= Kc) continue;
#pragma unroll
                for (int ni = 0; ni < 8; ni++) {
                    const int gn = nt * 128 + warp_n * 64 + ni * 8 + 2 * c0;
                    const int k1 = gn >> 6, c = gn & 63;
                    if (k1 >= Kc) continue;
                    float2 v = make_float2(acc[mi][ni][half_r * 2 + 0],
                                           acc[mi][ni][half_r * 2 + 1]);
                    *(float2*)(out + ((size_t)(b * Kc + k1) * Kc + k2) * Ch + c) = v;
                }
            }
        }
    }
}

// ---------------------------------------------------------------------------
extern "C" void kernel_launch(void* const* d_in, const int* in_sizes, int n_in,
                              void* d_out, int out_size) {
    const float* X = (const float*)d_in[0];
    float* out = (float*)d_out;

    cudaFuncSetAttribute(sp_gemm<1>, cudaFuncAttributeMaxDynamicSharedMemorySize, SMEM_GEMM);
    cudaFuncSetAttribute(sp_gemm<2>, cudaFuncAttributeMaxDynamicSharedMemorySize, SMEM_GEMM);

    sp_init<<<(Kc * Hn + 255) / 256, 256>>>();
    sp_transpose<<<dim3(256, 8, Bt), 256>>>(X);
    sp_gemm<1><<<dim3(2, 128, Bt), 256, SMEM_GEMM>>>(nullptr);  // Ys = W1 * Xs^T
    sp_gemm<2><<<dim3(1, 110, Bt), 256, SMEM_GEMM>>>(out);      // out = W2 * Ys^T
}

// round 16
// speedup vs baseline: 1.1205x; 1.1205x over previous
#include <cuda_runtime.h>
#include <cuda_fp16.h>
#include <cstdint>

// ============================================================================
// Spectral pooling as two plain-fp16 GEMMs (fp32 accumulate) on the legacy
// tensor path (mma.sync m16n8k16.f32.f16.f16.f32 — sm_100, no tcgen05).
//   out = A X A^T - B X B^T   (per batch, per channel)
// Stage 1: Ys[(k1,c)][(half,n2)] = W1[(half,k1)][n1] * Xs[(c,n2)][n1]   K=256
// Stage 2: out[k2][(k1,c)]       = W2[k2][(half,n2)] * Ys              K=512
// fp16 operands, fp32 accum; error ~4e-4 (model validated R12/R13).
// R16 = R15 resubmit (infra flake): CTA 128x128 (4 warps m64n64), 64KB smem,
// 2 CTAs/SM — overlap one CTA's prologue/sync/epilogue dead time with the
// other's MMA stream. Sibling mt CTAs (blockIdx.x fastest) share B via L2.
// ============================================================================

namespace {
constexpr int Hn = 256, Kc = 217, Bt = 16, Ch = 64;
constexpr int K1 = 256;      // stage-1 K (n1)
constexpr int K2 = 512;      // stage-2 K (half,n2)
constexpr int NC1 = 16384;   // stage-1 N  (c*256 + n2)
constexpr int YR  = 14080;   // stage-2 N padded (110*128 >= 217*64=13888)
constexpr double PI_D = 3.14159265358979323846;
}

__device__ __half g_W1s[512 * K1];               // rows>=434 stay 0
__device__ __half g_W2s[256 * K2];               // rows>=217 stay 0
__device__ __half g_Xs[(size_t)Bt * NC1 * K1];   // stage-1 B operand
__device__ __half g_Ys[(size_t)Bt * YR * K2];    // stage-2 B (pad rows 0)

#define SW128(x) ((x) ^ (((x) >> 3) & 0x70))

// ---------------- PTX helpers ------------------------------------------------
__device__ __forceinline__ uint32_t smem_u32(const void* p) {
    uint32_t a;
    asm("{ .reg .u64 t; cvta.to.shared.u64 t, %1; cvt.u32.u64 %0, t; }" : "=r"(a) : "l"(p));
    return a;
}
__device__ __forceinline__ void cp16(uint32_t dst, const void* src) {
    asm volatile("cp.async.cg.shared.global [%0], [%1], 16;" :: "r"(dst), "l"(src));
}
__device__ __forceinline__ void cp_commit() { asm volatile("cp.async.commit_group;"); }
template <int N>
__device__ __forceinline__ void cp_wait() {
    asm volatile("cp.async.wait_group %0;" :: "n"(N));
}
__device__ __forceinline__ void ldm_x4(uint32_t* r, uint32_t addr) {
    asm volatile("ldmatrix.sync.aligned.m8n8.x4.shared.b16 {%0,%1,%2,%3}, [%4];"
                 : "=r"(r[0]), "=r"(r[1]), "=r"(r[2]), "=r"(r[3]) : "r"(addr));
}
__device__ __forceinline__ void mma16816(float* c, const uint32_t* a,
                                         uint32_t b0, uint32_t b1) {
    asm volatile(
        "mma.sync.aligned.m16n8k16.row.col.f32.f16.f16.f32 "
        "{%0,%1,%2,%3}, {%4,%5,%6,%7}, {%8,%9}, {%0,%1,%2,%3};"
        : "+f"(c[0]), "+f"(c[1]), "+f"(c[2]), "+f"(c[3])
        : "r"(a[0]), "r"(a[1]), "r"(a[2]), "r"(a[3]), "r"(b0), "r"(b1));
}

// ---------------- init: fp16 weight tables ----------------------------------
__global__ void sp_init() {
    int idx = blockIdx.x * blockDim.x + threadIdx.x;
    if (idx >= Kc * Hn) return;
    int k = idx / Hn, n = idx - (idx / Hn) * Hn;
    double ph = PI_D * ((double)k / (double)Kc - (double)n / (double)Hn);
    double D = (k == 0 && n == 0) ? 1.0 : sin(217.0 * ph) / (sin(ph) * 217.0);
    double ang = 2.0 * PI_D * (double)n / (double)Hn;
    float a = (float)(D * cos(ang));
    float b = (float)(D * sin(ang));
    g_W1s[(size_t)k * K1 + n]        = __float2half(a);
    g_W1s[(size_t)(Kc + k) * K1 + n] = __float2half(b);
    g_W2s[(size_t)k * K2 + n]        = __float2half(a);
    g_W2s[(size_t)k * K2 + 256 + n]  = __float2half(-b);
}

// ---------------- transpose: X -> Xs[b][c*256+n2][n1] fp16 ------------------
__global__ __launch_bounds__(256) void sp_transpose(const float* __restrict__ X) {
    __shared__ float tile[32][65];
    const int n2  = blockIdx.x;   // 0..255
    const int n1g = blockIdx.y;   // 0..7
    const int b   = blockIdx.z;
    const int t   = threadIdx.x;
    const float* src = X + ((size_t)(b * Hn + n1g * 32)) * NC1 + n2 * 64;
#pragma unroll
    for (int p = 0; p < 8; p++) {
        int idx = p * 256 + t;
        int r = idx >> 6, col = idx & 63;
        tile[r][col] = src[(size_t)r * NC1 + col];
    }
    __syncthreads();
    const int c = t >> 2, part = t & 3, i0 = part * 8;
    __half* dst = g_Xs + ((size_t)b * NC1 + c * 256 + n2) * K1 + n1g * 32 + i0;
    __align__(16) __half h0[8];
#pragma unroll
    for (int i = 0; i < 8; i++) h0[i] = __float2half(tile[i0 + i][c]);
    *(uint4*)(dst) = *(const uint4*)h0;
}

// ---------------- warp-MMA GEMM: CTA 128x128, 4 warps m64n64, 2 CTAs/SM -----
// SMEM per stage: A 128x128B (16KB) + B 128x128B (16KB) = 32KB; 2 stages 64KB.
constexpr int ST_BYTES = 32768;
constexpr int SMEM_GEMM = 2 * ST_BYTES;   // 65536
constexpr int EP_STRIDE = 288;
constexpr int NTHR = 128;

template <int STAGE>
__global__ __launch_bounds__(NTHR, 2) void sp_gemm(float* __restrict__ out) {
    extern __shared__ char smem[];
    const uint32_t sb = smem_u32(smem);
    const int tid = threadIdx.x, lane = tid & 31, wid = tid >> 5;
    const int warp_m = wid >> 1, warp_n = wid & 1;   // 2 x 2 warp grid, m64n64
    const int mt = blockIdx.x, nt = blockIdx.y, b = blockIdx.z;

    constexpr int KT  = (STAGE == 1) ? K1 : K2;      // K (row stride, both ops)
    constexpr int NCH = KT / 64;                     // 4 / 8 chunks
    const __half* Arow = ((STAGE == 1) ? g_W1s : g_W2s) + (size_t)(mt * 128) * KT;
    const __half* Brow = ((STAGE == 1) ? (g_Xs + (size_t)b * NC1 * K1)
                                       : (g_Ys + (size_t)b * YR * K2))
                         + (size_t)(nt * 128) * KT;

    float acc[4][8][4];
#pragma unroll
    for (int i = 0; i < 4; i++)
#pragma unroll
        for (int j = 0; j < 8; j++)
#pragma unroll
            for (int q = 0; q < 4; q++) acc[i][j][q] = 0.f;

    auto prefetch = [&](int kc) {
        const uint32_t abase = sb + (kc & 1) * ST_BYTES;
        const uint32_t bbase = abase + 16384;
        // A: 128 rows x 128B = 1024 16B slots; 8 per thread
#pragma unroll
        for (int p = 0; p < 8; p++) {
            int slot = p * NTHR + tid;
            int r = slot >> 3, s = slot & 7;
            cp16(abase + SW128(r * 128 + s * 16),
                 Arow + (size_t)r * KT + kc * 64 + s * 8);
        }
        // B: 128 rows x 128B = 1024 slots; 8 per thread
#pragma unroll
        for (int p = 0; p < 8; p++) {
            int slot = p * NTHR + tid;
            int r = slot >> 3, s = slot & 7;
            cp16(bbase + SW128(r * 128 + s * 16),
                 Brow + (size_t)r * KT + kc * 64 + s * 8);
        }
        cp_commit();
    };

    const int arow = warp_m * 64 + (lane & 7) + ((lane >> 3) & 1) * 8;
    const int akof = ((lane >> 4) & 1) * 16;
    const int brow = warp_n * 64 + (lane & 7) + ((lane >> 4) & 1) * 8;
    const int bkof = ((lane >> 3) & 1) * 16;

    prefetch(0);
    for (int kc = 0; kc < NCH; kc++) {
        cp_wait<0>();
        __syncthreads();               // single barrier per chunk
        if (kc + 1 < NCH) prefetch(kc + 1);
        const uint32_t abase = sb + (kc & 1) * ST_BYTES;
        const uint32_t bbase = abase + 16384;
#pragma unroll
        for (int ks = 0; ks < 4; ks++) {
            const int kb0 = ks * 32;
            uint32_t af[4][4];
#pragma unroll
            for (int mi = 0; mi < 4; mi++)
                ldm_x4(af[mi], abase + SW128((arow + mi * 16) * 128 + kb0 + akof));
            uint32_t bf[4][4];
#pragma unroll
            for (int nj = 0; nj < 4; nj++)
                ldm_x4(bf[nj], bbase + SW128((brow + nj * 16) * 128 + kb0 + bkof));
#pragma unroll
            for (int mi = 0; mi < 4; mi++)
#pragma unroll
                for (int ni = 0; ni < 8; ni++)
                    mma16816(acc[mi][ni], af[mi],
                             bf[ni >> 1][(ni & 1) * 2], bf[ni >> 1][(ni & 1) * 2 + 1]);
        }
    }

    // ---------------- epilogue ----------------
    const int r0 = lane >> 2;          // c-frag rows r0, r0+8
    const int c0 = lane & 3;           // c-frag col-pair index
    if (STAGE == 1) {
        // Stage through smem -> coalesced 16B fp16 stores.
        __half* Yb = g_Ys + (size_t)b * YR * K2;
        __syncthreads();
#pragma unroll
        for (int mi = 0; mi < 4; mi++) {
#pragma unroll
            for (int half_r = 0; half_r < 2; half_r++) {
                const int row = warp_m * 64 + mi * 16 + r0 + half_r * 8;
#pragma unroll
                for (int ni = 0; ni < 8; ni++) {
                    const int cp = warp_n * 32 + ni * 4 + c0;  // col pair 0..63
                    __half2 p;
                    p.x = __float2half(acc[mi][ni][half_r * 2 + 0]);
                    p.y = __float2half(acc[mi][ni][half_r * 2 + 1]);
                    *(__half2*)(smem + row * EP_STRIDE + cp * 4) = p;
                }
            }
        }
        __syncthreads();
        // Coalesced copy: 128 rows x 16 x 16B units = 2048; 16 per thread.
#pragma unroll
        for (int p = 0; p < 16; p++) {
            const int u = p * NTHR + tid;
            const int row = u >> 4, sl = u & 15;
            const int gr = mt * 128 + row;
            if (gr < 434) {
                const int hf = (gr >= Kc) ? 1 : 0;
                const int k1 = gr - hf * Kc;
                const int gn = nt * 128 + sl * 8;
                const int c = gn >> 8, n2 = gn & 255;
                uint4 v = *(const uint4*)(smem + row * EP_STRIDE + sl * 16);
                *(uint4*)(Yb + ((size_t)k1 * 64 + c) * K2 + hf * 256 + n2) = v;
            }
        }
    } else {
#pragma unroll
        for (int mi = 0; mi < 4; mi++) {
#pragma unroll
            for (int half_r = 0; half_r < 2; half_r++) {
                const int k2 = mt * 128 + warp_m * 64 + mi * 16 + r0 + half_r * 8;
                if (k2 >= Kc) continue;
#pragma unroll
                for (int ni = 0; ni < 8; ni++) {
                    const int gn = nt * 128 + warp_n * 64 + ni * 8 + 2 * c0;
                    const int k1 = gn >> 6, c = gn & 63;
                    if (k1 >= Kc) continue;
                    float2 v = make_float2(acc[mi][ni][half_r * 2 + 0],
                                           acc[mi][ni][half_r * 2 + 1]);
                    *(float2*)(out + ((size_t)(b * Kc + k1) * Kc + k2) * Ch + c) = v;
                }
            }
        }
    }
}

// ---------------------------------------------------------------------------
extern "C" void kernel_launch(void* const* d_in, const int* in_sizes, int n_in,
                              void* d_out, int out_size) {
    const float* X = (const float*)d_in[0];
    float* out = (float*)d_out;

    cudaFuncSetAttribute(sp_gemm<1>, cudaFuncAttributeMaxDynamicSharedMemorySize, SMEM_GEMM);
    cudaFuncSetAttribute(sp_gemm<2>, cudaFuncAttributeMaxDynamicSharedMemorySize, SMEM_GEMM);

    sp_init<<<(Kc * Hn + 255) / 256, 256>>>();
    sp_transpose<<<dim3(256, 8, Bt), 256>>>(X);
    sp_gemm<1><<<dim3(4, 128, Bt), NTHR, SMEM_GEMM>>>(nullptr);  // Ys = W1 * Xs^T
    sp_gemm<2><<<dim3(2, 110, Bt), NTHR, SMEM_GEMM>>>(out);      // out = W2 * Ys^T
}